// round 6
// baseline (speedup 1.0000x reference)
#include <cuda_runtime.h>

// Fixed problem shape
constexpr int B_  = 32;
constexpr int C_  = 256;
constexpr int N_  = 4608;         // 96*48
constexpr int N4  = N_ / 4;       // 1152

// Batch split for L2 producer->consumer reuse (75.5 MB/half)
constexpr int SPLITS = 2;
constexpr int BH     = B_ / SPLITS;   // 16

// k1: one n per thread, C split into quarters across blocks
constexpr int K1_THREADS = 128;
constexpr int NT1        = N_ / K1_THREADS;   // 36
constexpr int CH         = 4;                 // channel quarters
constexpr int CHC        = C_ / CH;           // 64 channels per block
constexpr int K1_UNROLL  = 16;

// k2: per-batch merge + reduce
constexpr int K2_THREADS = 256;
constexpr int K2_ITERS   = N_ / K2_THREADS;   // 18

// k3: 2 channels per block, theta staged in smem, reversed traversal
constexpr int K3_CG      = 2;
constexpr int K3_TPC     = 384;               // threads per channel
constexpr int K3_THREADS = K3_CG * K3_TPC;    // 768
constexpr int NCG3       = C_ / K3_CG;        // 128

// Scratch (__device__ globals: allocation-free rule)
__device__ float g_gh[CH][B_ * N_];    // partial g dots
__device__ float g_ph[CH][B_ * N_];    // partial phi dots
__device__ float g_th[CH][B_ * N_];    // partial theta dots
__device__ float g_theta[B_ * N_];     // merged theta (+bias)
__device__ float g_s[B_];

// ---------------------------------------------------------------------------
// Kernel 1: partial channel dots over a 64-channel quarter. No reductions.
// ---------------------------------------------------------------------------
__global__ __launch_bounds__(K1_THREADS)
void k1_dots(const float* __restrict__ x,
             const float* __restrict__ gw,
             const float* __restrict__ tw,
             const float* __restrict__ pw,
             int bbase)
{
    __shared__ float swt[3 * CHC];
    const int tid = threadIdx.x;
    const int ch  = blockIdx.y;            // channel quarter
    if (tid < CHC) {
        swt[tid]           = gw[ch * CHC + tid];
        swt[CHC + tid]     = tw[ch * CHC + tid];
        swt[2 * CHC + tid] = pw[ch * CHC + tid];
    }
    __syncthreads();

    const int t = blockIdx.x;
    const int b = bbase + blockIdx.z;
    const int n = t * K1_THREADS + tid;

    const float* xr = x + ((size_t)b * C_ + (size_t)ch * CHC) * N_ + n;

    float ga = 0.f, ta = 0.f, pa = 0.f;

    #pragma unroll
    for (int c0 = 0; c0 < CHC; c0 += K1_UNROLL) {
        float xv[K1_UNROLL];
        #pragma unroll
        for (int j = 0; j < K1_UNROLL; j++)
            xv[j] = __ldg(xr + (size_t)(c0 + j) * N_);
        #pragma unroll
        for (int j = 0; j < K1_UNROLL; j++) {
            const int c = c0 + j;
            ga = fmaf(swt[c],           xv[j], ga);
            ta = fmaf(swt[CHC + c],     xv[j], ta);
            pa = fmaf(swt[2 * CHC + c], xv[j], pa);
        }
    }

    const size_t o = (size_t)b * N_ + n;
    g_gh[ch][o] = ga;
    g_th[ch][o] = ta;
    g_ph[ch][o] = pa;
}

// ---------------------------------------------------------------------------
// Kernel 2: per batch — merge theta quarters (+bias), compute s[b].
// All inputs are L2-resident partials. Deterministic reduction order.
// ---------------------------------------------------------------------------
__global__ __launch_bounds__(K2_THREADS)
void k2_merge(const float* __restrict__ gb, const float* __restrict__ tb,
              const float* __restrict__ pb, int bbase)
{
    const int b   = bbase + blockIdx.x;
    const int tid = threadIdx.x;
    const float gb0 = __ldg(gb), tb0 = __ldg(tb), pb0 = __ldg(pb);

    float s = 0.f;
    #pragma unroll
    for (int k = 0; k < K2_ITERS; k++) {
        const size_t o = (size_t)b * N_ + k * K2_THREADS + tid;
        const float gv = ((g_gh[0][o] + g_gh[1][o]) + (g_gh[2][o] + g_gh[3][o])) + gb0;
        const float pv = ((g_ph[0][o] + g_ph[1][o]) + (g_ph[2][o] + g_ph[3][o])) + pb0;
        g_theta[o] = ((g_th[0][o] + g_th[1][o]) + (g_th[2][o] + g_th[3][o])) + tb0;
        s = fmaf(gv, pv, s);
    }

    #pragma unroll
    for (int off = 16; off > 0; off >>= 1)
        s += __shfl_xor_sync(0xffffffffu, s, off);

    __shared__ float red[K2_THREADS / 32];
    if ((tid & 31) == 0) red[tid >> 5] = s;
    __syncthreads();
    if (tid == 0) {
        float acc = 0.f;
        #pragma unroll
        for (int w = 0; w < K2_THREADS / 32; w++) acc += red[w];
        g_s[b] = acc / (float)N_;
    }
}

// ---------------------------------------------------------------------------
// Kernel 3: z = theta[b,n]*ca + cd + x[b,c,n].
// 2 channels per block (concurrent warp groups), theta staged in smem.
// Blocks traverse (b, c) in REVERSE so first-scheduled blocks read the
// most-recently cached (L2-resident) tail of x written/read by k1.
// ---------------------------------------------------------------------------
__global__ __launch_bounds__(K3_THREADS)
void k3_epilogue(const float* __restrict__ x, float* __restrict__ z,
                 const float* __restrict__ Ww, const float* __restrict__ Wb,
                 const float* __restrict__ gamma, const float* __restrict__ beta,
                 const float* __restrict__ mean,  const float* __restrict__ var,
                 int bbase)
{
    __shared__ float4 sth[N4];          // theta row, 18.4 KB

    const int tid  = threadIdx.x;
    const int cg   = (NCG3 - 1) - (int)blockIdx.x;     // reversed c-group
    const int b    = bbase + (BH - 1) - (int)blockIdx.y; // reversed batch
    const int half = tid / K3_TPC;                     // 0 or 1
    const int lane = tid - half * K3_TPC;
    const int c    = cg * K3_CG + half;

    // stage theta row (768 + 384 loads)
    const float4* th = reinterpret_cast<const float4*>(g_theta) + (size_t)b * N4;
    sth[tid] = __ldg(th + tid);
    if (tid < N4 - K3_THREADS) sth[K3_THREADS + tid] = __ldg(th + K3_THREADS + tid);
    __syncthreads();

    const float inv = __ldg(gamma + c) * rsqrtf(__ldg(var + c) + 1e-5f);
    const float ca  = g_s[b] * __ldg(Ww + c) * inv;
    const float cd  = (__ldg(Wb + c) - __ldg(mean + c)) * inv + __ldg(beta + c);

    const size_t row = ((size_t)b * C_ + c) * N4;
    const float4* xr = reinterpret_cast<const float4*>(x) + row;
    float4*       zr = reinterpret_cast<float4*>(z) + row;

    #pragma unroll
    for (int k = 0; k < N4 / K3_TPC; k++) {
        const int i = k * K3_TPC + lane;
        const float4 tv = sth[i];
        const float4 xv = __ldcs(xr + i);      // last use: evict-first
        float4 o;
        o.x = fmaf(tv.x, ca, cd) + xv.x;
        o.y = fmaf(tv.y, ca, cd) + xv.y;
        o.z = fmaf(tv.z, ca, cd) + xv.z;
        o.w = fmaf(tv.w, ca, cd) + xv.w;
        __stcs(zr + i, o);                     // streaming store
    }
}

// ---------------------------------------------------------------------------
extern "C" void kernel_launch(void* const* d_in, const int* in_sizes, int n_in,
                              void* d_out, int out_size)
{
    const float* x     = (const float*)d_in[0];
    const float* g_w   = (const float*)d_in[1];
    const float* g_b   = (const float*)d_in[2];
    const float* th_w  = (const float*)d_in[3];
    const float* th_b  = (const float*)d_in[4];
    const float* ph_w  = (const float*)d_in[5];
    const float* ph_b  = (const float*)d_in[6];
    const float* W_w   = (const float*)d_in[7];
    const float* W_b   = (const float*)d_in[8];
    const float* gamma = (const float*)d_in[9];
    const float* beta  = (const float*)d_in[10];
    const float* mean  = (const float*)d_in[11];
    const float* var   = (const float*)d_in[12];
    float* z = (float*)d_out;

    for (int h = 0; h < SPLITS; h++) {
        const int bbase = h * BH;
        dim3 g1(NT1, CH, BH);
        k1_dots<<<g1, K1_THREADS>>>(x, g_w, th_w, ph_w, bbase);
        k2_merge<<<BH, K2_THREADS>>>(g_b, th_b, ph_b, bbase);
        dim3 g3(NCG3, BH);
        k3_epilogue<<<g3, K3_THREADS>>>(x, z, W_w, W_b, gamma, beta, mean, var, bbase);
    }
}

// round 7
// speedup vs baseline: 1.2463x; 1.2463x over previous
#include <cuda_runtime.h>

// Fixed problem shape
constexpr int B_  = 32;
constexpr int C_  = 256;
constexpr int N_  = 4608;         // 96*48
constexpr int N4  = N_ / 4;       // 1152
constexpr int N2  = N_ / 2;       // 2304 float2 per row

// Batch split for L2 producer->consumer reuse
constexpr int SPLITS = 2;
constexpr int BH     = B_ / SPLITS;   // 16

// k1: float2 per thread (2 n), C split in quarters
constexpr int K1T       = 128;
constexpr int CH        = 4;
constexpr int CHC       = C_ / CH;    // 64 channels per block
constexpr int NTM       = N2 / K1T;   // 18 tiles (256 n each)
constexpr int K1_UNROLL = 16;

// k3: one (b,c) row per block
constexpr int K3T = 384;

// Scratch (__device__ globals: allocation-free rule)
__device__ float2   g_G[CH][B_ * N2];
__device__ float2   g_P[CH][B_ * N2];
__device__ float2   g_T[CH][B_ * N2];
__device__ float    g_theta[B_ * N_];
__device__ float    g_sp[B_ * NTM];
__device__ unsigned g_cnt[B_ * NTM];   // zero-init; self-resetting

// ---------------------------------------------------------------------------
// Kernel 1: partial dots over a 64-channel quarter (float2 per thread).
// Last-arriving block of each (b,tile) merges the CH partials: writes theta
// (+bias) and the tile's sum(phi*g) partial. Deterministic (fixed-order math
// on identical data regardless of which block merges).
// ---------------------------------------------------------------------------
__global__ __launch_bounds__(K1T)
void k1_dots(const float* __restrict__ x,
             const float* __restrict__ gw, const float* __restrict__ gb,
             const float* __restrict__ tw, const float* __restrict__ tb,
             const float* __restrict__ pw, const float* __restrict__ pb,
             int bbase)
{
    __shared__ float swt[3 * CHC];
    const int tid  = threadIdx.x;
    const int tile = blockIdx.x;
    const int ch   = blockIdx.y;
    const int b    = bbase + blockIdx.z;

    if (tid < CHC) {
        swt[tid]           = gw[ch * CHC + tid];
        swt[CHC + tid]     = tw[ch * CHC + tid];
        swt[2 * CHC + tid] = pw[ch * CHC + tid];
    }
    __syncthreads();

    const int n2 = tile * K1T + tid;
    const float2* xr = reinterpret_cast<const float2*>(x)
                       + ((size_t)b * C_ + (size_t)ch * CHC) * N2 + n2;

    float2 ga = make_float2(0.f, 0.f);
    float2 ta = make_float2(0.f, 0.f);
    float2 pa = make_float2(0.f, 0.f);

    #pragma unroll
    for (int c0 = 0; c0 < CHC; c0 += K1_UNROLL) {
        float2 xv[K1_UNROLL];
        #pragma unroll
        for (int j = 0; j < K1_UNROLL; j++)
            xv[j] = __ldg(xr + (size_t)(c0 + j) * N2);
        #pragma unroll
        for (int j = 0; j < K1_UNROLL; j++) {
            const int c = c0 + j;
            const float w0 = swt[c];
            const float w1 = swt[CHC + c];
            const float w2 = swt[2 * CHC + c];
            ga.x = fmaf(w0, xv[j].x, ga.x); ga.y = fmaf(w0, xv[j].y, ga.y);
            ta.x = fmaf(w1, xv[j].x, ta.x); ta.y = fmaf(w1, xv[j].y, ta.y);
            pa.x = fmaf(w2, xv[j].x, pa.x); pa.y = fmaf(w2, xv[j].y, pa.y);
        }
    }

    const size_t o = (size_t)b * N2 + n2;
    g_G[ch][o] = ga;
    g_T[ch][o] = ta;
    g_P[ch][o] = pa;

    // -------- last-arriver merge (threadFenceReduction pattern) --------
    __threadfence();
    __syncthreads();
    __shared__ int sLast;
    if (tid == 0) {
        const int idx = b * NTM + tile;
        const unsigned old = atomicAdd(&g_cnt[idx], 1u);
        const int last = (old == CH - 1);
        if (last) g_cnt[idx] = 0;          // self-reset for next launch
        sLast = last;
    }
    __syncthreads();
    if (!sLast) return;

    const float gb0 = __ldg(gb), tb0 = __ldg(tb), pb0 = __ldg(pb);

    float2 G = make_float2(gb0, gb0);
    float2 P = make_float2(pb0, pb0);
    float2 T = make_float2(tb0, tb0);
    #pragma unroll
    for (int h = 0; h < CH; h++) {         // fixed order
        const float2 gv = g_G[h][o]; G.x += gv.x; G.y += gv.y;
        const float2 pv = g_P[h][o]; P.x += pv.x; P.y += pv.y;
        const float2 tv = g_T[h][o]; T.x += tv.x; T.y += tv.y;
    }
    reinterpret_cast<float2*>(g_theta)[o] = T;

    float pg = G.x * P.x + G.y * P.y;
    #pragma unroll
    for (int off = 16; off > 0; off >>= 1)
        pg += __shfl_xor_sync(0xffffffffu, pg, off);

    __shared__ float red[K1T / 32];
    if ((tid & 31) == 0) red[tid >> 5] = pg;
    __syncthreads();
    if (tid == 0) {
        float s = 0.f;
        #pragma unroll
        for (int w = 0; w < K1T / 32; w++) s += red[w];
        g_sp[b * NTM + tile] = s;
    }
}

// ---------------------------------------------------------------------------
// Kernel 3: z = theta[b,n]*ca + cd + x[b,c,n], one (b,c) row per block.
// s[b] summed per block from 18 tile partials (fixed order, L2 broadcast).
// ---------------------------------------------------------------------------
__global__ __launch_bounds__(K3T)
void k3_epilogue(const float* __restrict__ x, float* __restrict__ z,
                 const float* __restrict__ Ww, const float* __restrict__ Wb,
                 const float* __restrict__ gamma, const float* __restrict__ beta,
                 const float* __restrict__ mean,  const float* __restrict__ var,
                 int bbase)
{
    const int c = blockIdx.x;
    const int b = bbase + blockIdx.y;

    float s = 0.f;
    #pragma unroll
    for (int t = 0; t < NTM; t++) s += g_sp[b * NTM + t];   // fixed order
    s *= (1.f / (float)N_);

    const float inv = __ldg(gamma + c) * rsqrtf(__ldg(var + c) + 1e-5f);
    const float ca  = s * __ldg(Ww + c) * inv;
    const float cd  = (__ldg(Wb + c) - __ldg(mean + c)) * inv + __ldg(beta + c);

    const size_t row = ((size_t)b * C_ + c) * N4;
    const float4* xr = reinterpret_cast<const float4*>(x) + row;
    float4*       zr = reinterpret_cast<float4*>(z) + row;
    const float4* th = reinterpret_cast<const float4*>(g_theta) + (size_t)b * N4;

    #pragma unroll
    for (int k = 0; k < N4 / K3T; k++) {
        const int i = k * K3T + threadIdx.x;
        const float4 tv = __ldg(th + i);
        const float4 xv = __ldcs(xr + i);      // last use: evict-first
        float4 o;
        o.x = fmaf(tv.x, ca, cd) + xv.x;
        o.y = fmaf(tv.y, ca, cd) + xv.y;
        o.z = fmaf(tv.z, ca, cd) + xv.z;
        o.w = fmaf(tv.w, ca, cd) + xv.w;
        __stcs(zr + i, o);                     // streaming store
    }
}

// ---------------------------------------------------------------------------
extern "C" void kernel_launch(void* const* d_in, const int* in_sizes, int n_in,
                              void* d_out, int out_size)
{
    const float* x     = (const float*)d_in[0];
    const float* g_w   = (const float*)d_in[1];
    const float* g_b   = (const float*)d_in[2];
    const float* th_w  = (const float*)d_in[3];
    const float* th_b  = (const float*)d_in[4];
    const float* ph_w  = (const float*)d_in[5];
    const float* ph_b  = (const float*)d_in[6];
    const float* W_w   = (const float*)d_in[7];
    const float* W_b   = (const float*)d_in[8];
    const float* gamma = (const float*)d_in[9];
    const float* beta  = (const float*)d_in[10];
    const float* mean  = (const float*)d_in[11];
    const float* var   = (const float*)d_in[12];
    float* z = (float*)d_out;

    for (int h = 0; h < SPLITS; h++) {
        const int bbase = h * BH;
        dim3 g1(NTM, CH, BH);
        k1_dots<<<g1, K1T>>>(x, g_w, g_b, th_w, th_b, ph_w, ph_b, bbase);
        dim3 g3(C_, BH);
        k3_epilogue<<<g3, K3T>>>(x, z, W_w, W_b, gamma, beta, mean, var, bbase);
    }
}